// round 6
// baseline (speedup 1.0000x reference)
#include <cuda_runtime.h>
#include <cstdint>
#include <cstddef>

typedef unsigned long long u64;
typedef unsigned int u32;

#define B_SZ 64
#define T_SZ 2048
#define H_SZ 256
#define G4   1024   // 4*H

// 512MB scratch for xg = x @ W_i + bias  (static __device__ scratch is allowed)
__device__ float g_xg[(size_t)B_SZ * T_SZ * G4];

// ---------------- f32x2 helpers ----------------
__device__ __forceinline__ u64 pk2(float lo, float hi) {
    u64 r; asm("mov.b64 %0, {%1, %2};" : "=l"(r) : "f"(lo), "f"(hi)); return r;
}
__device__ __forceinline__ u64 dup2(float a) {
    u64 r; asm("mov.b64 %0, {%1, %1};" : "=l"(r) : "f"(a)); return r;
}
__device__ __forceinline__ u64 fma2(u64 a, u64 b, u64 c) {
    u64 d; asm("fma.rn.f32x2 %0, %1, %2, %3;" : "=l"(d) : "l"(a), "l"(b), "l"(c)); return d;
}
__device__ __forceinline__ u64 add2(u64 a, u64 b) {
    u64 d; asm("add.rn.f32x2 %0, %1, %2;" : "=l"(d) : "l"(a), "l"(b)); return d;
}
__device__ __forceinline__ void unpk(u64 v, float& lo, float& hi) {
    asm("mov.b64 {%0, %1}, %2;" : "=f"(lo), "=f"(hi) : "l"(v));
}

// ---------------- cluster / DSMEM helpers ----------------
__device__ __forceinline__ u32 smem_u32(const void* p) {
    u32 a;
    asm("{ .reg .u64 t; cvta.to.shared.u64 t, %1; cvt.u32.u64 %0, t; }" : "=r"(a) : "l"(p));
    return a;
}
__device__ __forceinline__ u32 mapa_sh(u32 a, u32 rk) {
    u32 r; asm("mapa.shared::cluster.u32 %0, %1, %2;" : "=r"(r) : "r"(a), "r"(rk)); return r;
}
__device__ __forceinline__ void stc_f32(u32 a, float v) {
    asm volatile("st.shared::cluster.f32 [%0], %1;" :: "r"(a), "f"(v) : "memory");
}
__device__ __forceinline__ void cluster_sync_() {
    asm volatile("barrier.cluster.arrive.aligned;" ::: "memory");
    asm volatile("barrier.cluster.wait.aligned;" ::: "memory");
}

// ---------------- activations ----------------
__device__ __forceinline__ float sigm(float x) {
    return __fdividef(1.0f, 1.0f + __expf(-x));
}
__device__ __forceinline__ float tanh_(float x) {
    return 1.0f - __fdividef(2.0f, __expf(2.0f * x) + 1.0f);
}

// =====================================================================
// Phase 1: g_xg[m][1024] = x[m][256] @ W_i[256][1024] + bias
// 128x128 tile, 256 threads, 8x8 microtile, f32x2 accumulators
// =====================================================================
__global__ __launch_bounds__(256, 2) void xw_gemm(
    const float* __restrict__ A,      // x    [131072, 256]
    const float* __restrict__ W,      // W_i  [256, 1024]
    const float* __restrict__ bias)   // [1024]
{
    __shared__ float As[32][132];   // [k][m], padded
    __shared__ float Bs[32][132];   // [k][n], padded

    const int tid = threadIdx.x;
    const int tx = tid & 15;        // n microtile idx
    const int ty = tid >> 4;        // m microtile idx
    const int mBase = blockIdx.y * 128;
    const int nBase = blockIdx.x * 128;

    u64 acc[8][4];
    {
        const float* bp = bias + nBase + tx * 8;
        u64 b0 = pk2(bp[0], bp[1]);
        u64 b1 = pk2(bp[2], bp[3]);
        u64 b2 = pk2(bp[4], bp[5]);
        u64 b3 = pk2(bp[6], bp[7]);
#pragma unroll
        for (int i = 0; i < 8; i++) { acc[i][0] = b0; acc[i][1] = b1; acc[i][2] = b2; acc[i][3] = b3; }
    }

    for (int kc = 0; kc < 8; kc++) {
#pragma unroll
        for (int i = 0; i < 4; i++) {
            int fidx = tid + i * 256;
            // A tile: 128 rows x 32 k  (float4 along k, transpose-scatter into As)
            int row = fidx >> 3, kq = fidx & 7;
            float4 av = *(const float4*)(A + (size_t)(mBase + row) * 256 + kc * 32 + kq * 4);
            As[kq * 4 + 0][row] = av.x;
            As[kq * 4 + 1][row] = av.y;
            As[kq * 4 + 2][row] = av.z;
            As[kq * 4 + 3][row] = av.w;
            // B tile: 32 k x 128 n
            int k = fidx >> 5, nq = fidx & 31;
            float4 bv = *(const float4*)(W + (size_t)(kc * 32 + k) * 1024 + nBase + nq * 4);
            *(float4*)&Bs[k][nq * 4] = bv;
        }
        __syncthreads();
#pragma unroll
        for (int k = 0; k < 32; k++) {
            float4 a0 = *(float4*)&As[k][ty * 8];
            float4 a1 = *(float4*)&As[k][ty * 8 + 4];
            float4 b0 = *(float4*)&Bs[k][tx * 8];
            float4 b1 = *(float4*)&Bs[k][tx * 8 + 4];
            u64 bb0 = pk2(b0.x, b0.y), bb1 = pk2(b0.z, b0.w);
            u64 bb2 = pk2(b1.x, b1.y), bb3 = pk2(b1.z, b1.w);
            float aa[8] = {a0.x, a0.y, a0.z, a0.w, a1.x, a1.y, a1.z, a1.w};
#pragma unroll
            for (int i = 0; i < 8; i++) {
                u64 ad = dup2(aa[i]);
                acc[i][0] = fma2(ad, bb0, acc[i][0]);
                acc[i][1] = fma2(ad, bb1, acc[i][1]);
                acc[i][2] = fma2(ad, bb2, acc[i][2]);
                acc[i][3] = fma2(ad, bb3, acc[i][3]);
            }
        }
        __syncthreads();
    }

#pragma unroll
    for (int i = 0; i < 8; i++) {
        float o[8];
        unpk(acc[i][0], o[0], o[1]); unpk(acc[i][1], o[2], o[3]);
        unpk(acc[i][2], o[4], o[5]); unpk(acc[i][3], o[6], o[7]);
        float* cp = g_xg + (size_t)(mBase + ty * 8 + i) * 1024 + nBase + tx * 8;
        *(float4*)(cp)     = make_float4(o[0], o[1], o[2], o[3]);
        *(float4*)(cp + 4) = make_float4(o[4], o[5], o[6], o[7]);
    }
}

// =====================================================================
// Phase 2: recurrent scan. Grid (8,16), cluster (8,1,1).
// Cluster grp owns batch rows 4*grp..4*grp+3; CTA rank owns units
// [rank*32, rank*32+32). 256 threads: tid = ks*32 + j (k-slice ks, unit j);
// W_h slice (32 k x 1 unit x 4 gates) in registers = 64 u64/thread.
// Per step: FFMA2 partial GEMM -> smem k-reduce -> 128 owner threads
// (rr=tid>>5 = row, j) do activations (c in reg), write h to out, and
// broadcast h to all 8 CTAs' double-buffered hbuf via DSMEM; one
// cluster.sync per step provides all ordering.
// =====================================================================
__global__ __launch_bounds__(256, 1) __cluster_dims__(8, 1, 1)
void lstm_scan(const float* __restrict__ Wh, float* __restrict__ out)
{
    __shared__ float4 hbuf[2][H_SZ];     // [parity][unit] = h of the 4 rows
    __shared__ u64 red[256][9];          // per-thread partials, padded

    const int tid  = threadIdx.x;
    const int rank = blockIdx.x;         // 0..7 within cluster
    const int grp  = blockIdx.y;         // 0..15 batch group
    const int ks   = tid >> 5;           // k slice 0..7
    const int j    = tid & 31;           // unit within CTA
    const int u    = rank * 32 + j;      // global hidden unit

    // --- W_h slice into registers: 64 u64 = 128 floats/thread ---
    u64 wp[64];
#pragma unroll
    for (int kk = 0; kk < 32; kk++) {
        const float* wr = Wh + (size_t)(ks * 32 + kk) * 1024 + u;
        wp[2 * kk + 0] = pk2(wr[0],   wr[256]);   // (i, f)
        wp[2 * kk + 1] = pk2(wr[512], wr[768]);   // (g, o)
    }

    // owner-thread state (valid for tid < 128)
    const int rr  = tid >> 5;                    // row within group 0..3
    const int row = grp * 4 + rr;                // global batch row
    const size_t xgBase  = (size_t)row * T_SZ * 1024 + u;
    const size_t outBase = (size_t)row * T_SZ * H_SZ + u;
    float c = 0.0f, h = 0.0f;

    hbuf[0][tid] = make_float4(0.f, 0.f, 0.f, 0.f);
    __syncthreads();

    // remote hbuf base addresses for all 8 cluster CTAs
    const u32 hb_l = smem_u32(&hbuf[0][0]);
    u32 hrem[8];
#pragma unroll
    for (int rk = 0; rk < 8; rk++) hrem[rk] = mapa_sh(hb_l, (u32)rk);

    int p = 0;
#pragma unroll 1
    for (int t = 0; t < T_SZ; t++) {
        // prefetch xg for this step (latency hidden under the FMA loop)
        float xi = 0.f, xf = 0.f, xgg = 0.f, xo = 0.f;
        if (tid < 128) {
            const float* xp = g_xg + xgBase + (size_t)t * 1024;
            xi  = __ldg(xp);
            xf  = __ldg(xp + 256);
            xgg = __ldg(xp + 512);
            xo  = __ldg(xp + 768);
        }

        // partial GEMM over this thread's 32-k slice: 4 rows x 2 gate-pairs
        u64 acc[8];
#pragma unroll
        for (int e = 0; e < 8; e++) acc[e] = 0ull;
#pragma unroll
        for (int kk = 0; kk < 32; kk++) {
            float4 h4 = hbuf[p][(ks << 5) + kk];   // warp-broadcast LDS.128
            u64 w0 = wp[2 * kk], w1 = wp[2 * kk + 1];
            u64 d;
            d = dup2(h4.x); acc[0] = fma2(d, w0, acc[0]); acc[1] = fma2(d, w1, acc[1]);
            d = dup2(h4.y); acc[2] = fma2(d, w0, acc[2]); acc[3] = fma2(d, w1, acc[3]);
            d = dup2(h4.z); acc[4] = fma2(d, w0, acc[4]); acc[5] = fma2(d, w1, acc[5]);
            d = dup2(h4.w); acc[6] = fma2(d, w0, acc[6]); acc[7] = fma2(d, w1, acc[7]);
        }
#pragma unroll
        for (int e = 0; e < 8; e++) red[tid][e] = acc[e];
        __syncthreads();

        if (tid < 128) {
            // reduce over the 8 k-slices for (row rr, unit j)
            u64 s0 = red[j][rr * 2 + 0];
            u64 s1 = red[j][rr * 2 + 1];
#pragma unroll
            for (int s = 1; s < 8; s++) {
                s0 = add2(s0, red[s * 32 + j][rr * 2 + 0]);
                s1 = add2(s1, red[s * 32 + j][rr * 2 + 1]);
            }
            float gi, gf, gg, go;
            unpk(s0, gi, gf);
            unpk(s1, gg, go);
            gi += xi; gf += xf; gg += xgg; go += xo;

            c = sigm(gf) * c + sigm(gi) * tanh_(gg);
            h = sigm(go) * tanh_(c);

            out[outBase + (size_t)t * H_SZ] = h;

            // broadcast h into hbuf[p^1][u] component rr of all 8 CTAs
            const u32 off = (u32)(((p ^ 1) * H_SZ + u) * 16 + rr * 4);
#pragma unroll
            for (int rk = 0; rk < 8; rk++) stc_f32(hrem[rk] + off, h);
        }
        cluster_sync_();
        p ^= 1;
    }

    // finals: h_T then c_T, each [B, H], after Hs
    if (tid < 128) {
        float* fin = out + (size_t)B_SZ * T_SZ * H_SZ;
        fin[(size_t)row * H_SZ + u] = h;
        fin[(size_t)B_SZ * H_SZ + (size_t)row * H_SZ + u] = c;
    }
}

extern "C" void kernel_launch(void* const* d_in, const int* in_sizes, int n_in,
                              void* d_out, int out_size) {
    const float* x    = (const float*)d_in[0];
    const float* W_i  = (const float*)d_in[1];
    const float* W_h  = (const float*)d_in[2];
    const float* bias = (const float*)d_in[3];
    float* out = (float*)d_out;

    // Phase 1: xg = x @ W_i + bias   (M=131072, N=1024, K=256)
    dim3 g1(1024 / 128, (B_SZ * T_SZ) / 128);
    xw_gemm<<<g1, 256>>>(x, W_i, bias);

    // Phase 2: recurrent scan (16 clusters of 8 CTAs)
    dim3 g2(8, 16);
    lstm_scan<<<g2, 256>>>(W_h, out);
}

// round 7
// speedup vs baseline: 1.5242x; 1.5242x over previous
#include <cuda_runtime.h>
#include <cstdint>
#include <cstddef>

typedef unsigned long long u64;
typedef unsigned int u32;

#define B_SZ 64
#define T_SZ 2048
#define H_SZ 256
#define G4   1024   // 4*H

// 512MB scratch for xg, layout [row][t][u][gate] (gate-interleaved for float4 loads)
__device__ float g_xg[(size_t)B_SZ * T_SZ * G4];

// ---------------- f32x2 helpers ----------------
__device__ __forceinline__ u64 pk2(float lo, float hi) {
    u64 r; asm("mov.b64 %0, {%1, %2};" : "=l"(r) : "f"(lo), "f"(hi)); return r;
}
__device__ __forceinline__ u64 dup2(float a) {
    u64 r; asm("mov.b64 %0, {%1, %1};" : "=l"(r) : "f"(a)); return r;
}
__device__ __forceinline__ u64 fma2(u64 a, u64 b, u64 c) {
    u64 d; asm("fma.rn.f32x2 %0, %1, %2, %3;" : "=l"(d) : "l"(a), "l"(b), "l"(c)); return d;
}
__device__ __forceinline__ u64 add2(u64 a, u64 b) {
    u64 d; asm("add.rn.f32x2 %0, %1, %2;" : "=l"(d) : "l"(a), "l"(b)); return d;
}
__device__ __forceinline__ void unpk(u64 v, float& lo, float& hi) {
    asm("mov.b64 {%0, %1}, %2;" : "=f"(lo), "=f"(hi) : "l"(v));
}

// ---------------- cluster / mbarrier helpers ----------------
__device__ __forceinline__ u32 smem_u32(const void* p) {
    u32 a;
    asm("{ .reg .u64 t; cvta.to.shared.u64 t, %1; cvt.u32.u64 %0, t; }" : "=r"(a) : "l"(p));
    return a;
}
__device__ __forceinline__ u32 mapa_sh(u32 a, u32 rk) {
    u32 r; asm("mapa.shared::cluster.u32 %0, %1, %2;" : "=r"(r) : "r"(a), "r"(rk)); return r;
}
__device__ __forceinline__ void cluster_sync_() {
    asm volatile("barrier.cluster.arrive.aligned;" ::: "memory");
    asm volatile("barrier.cluster.wait.aligned;" ::: "memory");
}
__device__ __forceinline__ void mbar_init(u32 a, u32 cnt) {
    asm volatile("mbarrier.init.shared.b64 [%0], %1;" :: "r"(a), "r"(cnt) : "memory");
}
__device__ __forceinline__ void mbar_expect(u32 a, u32 bytes) {
    asm volatile("mbarrier.arrive.expect_tx.shared.b64 _, [%0], %1;" :: "r"(a), "r"(bytes) : "memory");
}
__device__ __forceinline__ void mbar_wait(u32 a, u32 ph) {
    asm volatile(
        "{\n\t.reg .pred P;\n\t"
        "MW%=:\n\t"
        "mbarrier.try_wait.parity.acquire.cta.shared::cta.b64 P, [%0], %1, 0x989680;\n\t"
        "@!P bra MW%=;\n\t}"
        :: "r"(a), "r"(ph) : "memory");
}
// remote store with tx-completion on the remote CTA's mbarrier
__device__ __forceinline__ void st_async_f32(u32 dst, float v, u32 mb) {
    asm volatile(
        "st.async.shared::cluster.mbarrier::complete_tx::bytes.b32 [%0], %1, [%2];"
        :: "r"(dst), "r"(__float_as_uint(v)), "r"(mb) : "memory");
}

// ---------------- activations (exact, MUFU-based) ----------------
__device__ __forceinline__ float sigm(float x) {
    return __fdividef(1.0f, 1.0f + __expf(-x));
}
__device__ __forceinline__ float tanh_(float x) {
    return 1.0f - __fdividef(2.0f, __expf(2.0f * x) + 1.0f);
}

// =====================================================================
// Phase 1: xg = x @ W_i + bias -> g_xg in [row][t][u][gate] layout
// 128x128 tile, 256 threads, 8x8 microtile, f32x2 accumulators
// =====================================================================
__global__ __launch_bounds__(256, 2) void xw_gemm(
    const float* __restrict__ A,      // x    [131072, 256]
    const float* __restrict__ W,      // W_i  [256, 1024]
    const float* __restrict__ bias)   // [1024]
{
    __shared__ float As[32][132];
    __shared__ float Bs[32][132];

    const int tid = threadIdx.x;
    const int tx = tid & 15;
    const int ty = tid >> 4;
    const int mBase = blockIdx.y * 128;
    const int nBase = blockIdx.x * 128;

    u64 acc[8][4];
    {
        const float* bp = bias + nBase + tx * 8;
        u64 b0 = pk2(bp[0], bp[1]);
        u64 b1 = pk2(bp[2], bp[3]);
        u64 b2 = pk2(bp[4], bp[5]);
        u64 b3 = pk2(bp[6], bp[7]);
#pragma unroll
        for (int i = 0; i < 8; i++) { acc[i][0] = b0; acc[i][1] = b1; acc[i][2] = b2; acc[i][3] = b3; }
    }

    for (int kc = 0; kc < 8; kc++) {
#pragma unroll
        for (int i = 0; i < 4; i++) {
            int fidx = tid + i * 256;
            int row = fidx >> 3, kq = fidx & 7;
            float4 av = *(const float4*)(A + (size_t)(mBase + row) * 256 + kc * 32 + kq * 4);
            As[kq * 4 + 0][row] = av.x;
            As[kq * 4 + 1][row] = av.y;
            As[kq * 4 + 2][row] = av.z;
            As[kq * 4 + 3][row] = av.w;
            int k = fidx >> 5, nq = fidx & 31;
            float4 bv = *(const float4*)(W + (size_t)(kc * 32 + k) * 1024 + nBase + nq * 4);
            *(float4*)&Bs[k][nq * 4] = bv;
        }
        __syncthreads();
#pragma unroll
        for (int k = 0; k < 32; k++) {
            float4 a0 = *(float4*)&As[k][ty * 8];
            float4 a1 = *(float4*)&As[k][ty * 8 + 4];
            float4 b0 = *(float4*)&Bs[k][tx * 8];
            float4 b1 = *(float4*)&Bs[k][tx * 8 + 4];
            u64 bb0 = pk2(b0.x, b0.y), bb1 = pk2(b0.z, b0.w);
            u64 bb2 = pk2(b1.x, b1.y), bb3 = pk2(b1.z, b1.w);
            float aa[8] = {a0.x, a0.y, a0.z, a0.w, a1.x, a1.y, a1.z, a1.w};
#pragma unroll
            for (int i = 0; i < 8; i++) {
                u64 ad = dup2(aa[i]);
                acc[i][0] = fma2(ad, bb0, acc[i][0]);
                acc[i][1] = fma2(ad, bb1, acc[i][1]);
                acc[i][2] = fma2(ad, bb2, acc[i][2]);
                acc[i][3] = fma2(ad, bb3, acc[i][3]);
            }
        }
        __syncthreads();
    }

    // epilogue: permute col (gate*256+u) -> u*4+gate so scan reads float4/unit
    const int gate = nBase >> 8;            // 128-blocks never cross a gate boundary
    const int uBase = (nBase & 255) + tx * 8;
#pragma unroll
    for (int i = 0; i < 8; i++) {
        float o[8];
        unpk(acc[i][0], o[0], o[1]); unpk(acc[i][1], o[2], o[3]);
        unpk(acc[i][2], o[4], o[5]); unpk(acc[i][3], o[6], o[7]);
        float* rowp = g_xg + (size_t)(mBase + ty * 8 + i) * 1024;
#pragma unroll
        for (int q = 0; q < 8; q++)
            rowp[(uBase + q) * 4 + gate] = o[q];
    }
}

// =====================================================================
// Phase 2: recurrent scan. Grid (8,16), cluster (8,1,1).
// Cluster grp owns batch rows 4*grp..4*grp+3; CTA rank owns units
// [32*rank, 32*rank+32). Thread map: warp w (0..7), lane = j4*8+ks:
//   unit u = rank*32 + w*4 + j4, k-slice ks (32 k's). Weights packed
//   along k in registers (64 u64/thread). Per step:
//   LDS.128 h-pairs + FFMA2 -> warp-shuffle reduce-scatter over ks ->
//   owner lanes (ks<4 => row ks) activations (c in reg) -> st.async h
//   to all 8 peer SMEMs with mbarrier tx-completion. No __syncthreads,
//   no cluster.sync in the loop.
// =====================================================================
__global__ __launch_bounds__(256, 1) __cluster_dims__(8, 1, 1)
void lstm_scan(const float* __restrict__ Wh, float* __restrict__ out)
{
    __shared__ u64 hbuf[2][4][128];   // [parity][row][k-pair slot] = (h[2k],h[2k+1])
    __shared__ u64 mbar[2];

    const int tid  = threadIdx.x;
    const int w    = tid >> 5;
    const int lane = tid & 31;
    const int j4   = lane >> 3;          // unit-within-group
    const int ks   = lane & 7;           // k-slice
    const int rank = blockIdx.x;
    const int grp  = blockIdx.y;
    const int u    = rank * 32 + w * 4 + j4;

    // --- weights packed along k: wp[g][m], k-pair kp = ks*16+m ---
    u64 wp[4][16];
#pragma unroll
    for (int m = 0; m < 16; m++) {
        const int kA = ks * 32 + 2 * m;
#pragma unroll
        for (int g = 0; g < 4; g++) {
            wp[g][m] = pk2(Wh[(size_t)kA * 1024 + g * 256 + u],
                           Wh[(size_t)(kA + 1) * 1024 + g * 256 + u]);
        }
    }

    // init: zero parity-0 buffer, init + arm both mbarriers
    {
        u64* hz = &hbuf[0][0][0];
        hz[tid] = 0ull; hz[tid + 256] = 0ull;
    }
    const u32 hb_l = smem_u32(&hbuf[0][0][0]);
    const u32 mb_l = smem_u32(&mbar[0]);
    if (tid == 0) {
        mbar_init(mb_l, 1);
        mbar_init(mb_l + 8, 1);
        mbar_expect(mb_l, 4096);       // buffer 0: fed by stores at t=1, used t=2
        mbar_expect(mb_l + 8, 4096);   // buffer 1: fed by stores at t=0, used t=1
    }
    __syncthreads();
    cluster_sync_();   // once: peers' barriers armed + hbuf[0] zeroed everywhere

    // owner-lane constants (ks<4 => row rr=ks)
    const int rowg = grp * 4 + ks;                       // global batch row (owners)
    const size_t xgBase  = ((size_t)rowg * T_SZ) * 1024 + (size_t)u * 4;
    const size_t outBase = ((size_t)rowg * T_SZ) * H_SZ + u;
    // producer slot for (row=ks, unit u):
    const int kp  = u >> 1;
    const int mq  = kp & 15;
    const u32 off0 = (u32)(ks * 1024 + ((mq >> 1) * 16 + (kp >> 4) * 2 + (mq & 1)) * 8 + (u & 1) * 4);

    u32 hdst[8], mrem[8];
#pragma unroll
    for (int rk = 0; rk < 8; rk++) {
        hdst[rk] = mapa_sh(hb_l, (u32)rk) + off0;
        mrem[rk] = mapa_sh(mb_l, (u32)rk);
    }

    float c = 0.0f, h = 0.0f;
    u32 ph0 = 0, ph1 = 0;

#pragma unroll 1
    for (int t = 0; t < T_SZ; t++) {
        const int b = t & 1;

        // xg prefetch for this step — issued BEFORE the barrier wait
        float4 xq = make_float4(0.f, 0.f, 0.f, 0.f);
        if (ks < 4)
            xq = *(const float4*)(g_xg + xgBase + (size_t)t * 1024);

        if (t > 0) {
            const u32 phb = b ? ph1 : ph0;
            mbar_wait(mb_l + (b << 3), phb);
            if (b) ph1 ^= 1; else ph0 ^= 1;
            if (tid == 0) mbar_expect(mb_l + (b << 3), 4096);  // re-arm for t+2
        }

        // ---- partial GEMM over this thread's 32-k slice ----
        u64 acc[4][4];
#pragma unroll
        for (int r = 0; r < 4; r++)
#pragma unroll
            for (int g = 0; g < 4; g++) acc[r][g] = 0ull;

        const u64* hbp = &hbuf[b][0][0];
#pragma unroll
        for (int m2 = 0; m2 < 8; m2++) {
#pragma unroll
            for (int r = 0; r < 4; r++) {
                ulonglong2 hv = *(const ulonglong2*)(hbp + r * 128 + m2 * 16 + ks * 2);
#pragma unroll
                for (int g = 0; g < 4; g++) {
                    acc[r][g] = fma2(hv.x, wp[g][2 * m2],     acc[r][g]);
                    acc[r][g] = fma2(hv.y, wp[g][2 * m2 + 1], acc[r][g]);
                }
            }
        }

        // ---- warp reduce-scatter over ks (lane ends with row ks&3) ----
        const bool pb = (ks & 1);
        const bool qb = (ks & 2);
        u64 kk[4];
#pragma unroll
        for (int g = 0; g < 4; g++) {
            // round 1 (xor 1): send rows of partner parity, keep own parity
            u64 sA = pb ? acc[0][g] : acc[1][g];
            u64 sB = pb ? acc[2][g] : acc[3][g];
            u64 rA = __shfl_xor_sync(0xffffffffu, sA, 1);
            u64 rB = __shfl_xor_sync(0xffffffffu, sB, 1);
            u64 k0 = add2(pb ? acc[1][g] : acc[0][g], rA);  // row pb
            u64 k1 = add2(pb ? acc[3][g] : acc[2][g], rB);  // row pb+2
            // round 2 (xor 2)
            u64 s2 = qb ? k0 : k1;
            u64 r2 = __shfl_xor_sync(0xffffffffu, s2, 2);
            u64 kx = add2(qb ? k1 : k0, r2);
            // round 3 (xor 4): full k
            kk[g] = add2(kx, __shfl_xor_sync(0xffffffffu, kx, 4));
        }

        // ---- owners: activations + output + broadcast ----
        if (ks < 4) {
            float e0, e1;
            unpk(kk[0], e0, e1); const float gi = e0 + e1 + xq.x;
            unpk(kk[1], e0, e1); const float gf = e0 + e1 + xq.y;
            unpk(kk[2], e0, e1); const float gg = e0 + e1 + xq.z;
            unpk(kk[3], e0, e1); const float go = e0 + e1 + xq.w;

            c = sigm(gf) * c + sigm(gi) * tanh_(gg);
            h = sigm(go) * tanh_(c);

            out[outBase + (size_t)t * H_SZ] = h;

            if (t < T_SZ - 1) {
                const u32 po = (u32)((b ^ 1) << 12);
                const u32 mo = (u32)((b ^ 1) << 3);
#pragma unroll
                for (int rk = 0; rk < 8; rk++)
                    st_async_f32(hdst[rk] + po, h, mrem[rk] + mo);
            }
        }
    }

    // finals: h_T then c_T, each [B, H], appended after Hs
    if (ks < 4) {
        float* fin = out + (size_t)B_SZ * T_SZ * H_SZ;
        fin[(size_t)rowg * H_SZ + u] = h;
        fin[(size_t)B_SZ * H_SZ + (size_t)rowg * H_SZ + u] = c;
    }
}

extern "C" void kernel_launch(void* const* d_in, const int* in_sizes, int n_in,
                              void* d_out, int out_size) {
    const float* x    = (const float*)d_in[0];
    const float* W_i  = (const float*)d_in[1];
    const float* W_h  = (const float*)d_in[2];
    const float* bias = (const float*)d_in[3];
    float* out = (float*)d_out;

    dim3 g1(1024 / 128, (B_SZ * T_SZ) / 128);
    xw_gemm<<<g1, 256>>>(x, W_i, bias);

    dim3 g2(8, 16);
    lstm_scan<<<g2, 256>>>(W_h, out);
}